// round 8
// baseline (speedup 1.0000x reference)
#include <cuda_runtime.h>
#include <cstdint>

#define NB 16
#define NS 2048
#define NH 512
#define NW 4
#define NL 2
#define NSP (NS + 2*NW)   // 2056
#define LN_EPS 1e-5f

#define BM 128
#define BN 128
#define BK 32
#define NTHREADS 256
#define ASTR 36    // BK + 4  -> conflict-free A fragment loads (stride%32 == 4)
#define BSTR 136   // BN + 8  -> conflict-free B fragment loads (stride%32 == 8)

// Scratch (device globals: allocation-free contract)
__device__ float g_padded[NB*NSP*NH];
__device__ float g_lo [NB*NS*NH];
__device__ float g_ro [NB*NS*NH];
__device__ float g_tmp[NB*NS*NH];
__device__ float g_hid[NB*NS*NH];

__device__ __forceinline__ uint32_t f2t(float x){
    uint32_t u; asm("cvt.rna.tf32.f32 %0, %1;" : "=r"(u) : "f"(x)); return u;
}

// Build padded [B, 2056, 512]: left_padding rows, inputs, right_padding rows.
__global__ void build_padded_kernel(const float* __restrict__ inp,
                                    const float* __restrict__ lp,
                                    const float* __restrict__ rp){
    int idx = blockIdx.x*blockDim.x + threadIdx.x;
    const int H4 = NH/4;
    const int total = NB*NSP*H4;
    if (idx >= total) return;
    int h4 = idx % H4;
    int r  = (idx / H4) % NSP;
    int b  = idx / (H4*NSP);
    float4 v;
    if (r < NW)            v = reinterpret_cast<const float4*>(lp)[r*H4 + h4];
    else if (r >= NW+NS)   v = reinterpret_cast<const float4*>(rp)[(r-NW-NS)*H4 + h4];
    else                   v = reinterpret_cast<const float4*>(inp)[((size_t)b*NS + (r-NW))*H4 + h4];
    reinterpret_cast<float4*>(g_padded)[idx] = v;
}

// Generic tf32 tensor-core GEMM: C[M=32768, N=512] = A[M,K] @ Bw[K,512]
// amode: 0 = dense A (row stride K); 1 = padded-left view; 2 = padded-right view
// mode : 0 = C = relu(acc + bias)
//        1 = r = resid + acc + bias; C = r; out_all[layer,s,b,colOff+c] = r;
//            (optional) out_last[b,s,colOff+c] = r
__global__ __launch_bounds__(NTHREADS) void gemm_tf32_kernel(
    const float* __restrict__ A, const float* __restrict__ Bw, const float* __restrict__ bias,
    float* __restrict__ C, const float* __restrict__ resid,
    float* __restrict__ out_all, float* __restrict__ out_last,
    int K, int amode, int mode, int colOff, int layer)
{
    __shared__ __align__(16) uint32_t As[BM*ASTR];
    __shared__ __align__(16) uint32_t Bs[BK*BSTR];

    const int tid   = threadIdx.x;
    const int lane  = tid & 31;
    const int warp  = tid >> 5;
    const int group = lane >> 2;
    const int tid4  = lane & 3;

    // Per-thread A row pointers (4 rows, fixed across k-tiles)
    const float* aptr[4];
    #pragma unroll
    for (int r = 0; r < 4; r++){
        int mrow = blockIdx.y*BM + (tid>>3) + r*32;
        if (amode == 0) aptr[r] = A + (size_t)mrow * K;
        else {
            int b = mrow >> 11, t = mrow & 2047;
            aptr[r] = A + ((size_t)b*NSP + t + (amode==2 ? (NW+1) : 0)) * NH;
        }
    }
    const int ak    = (tid & 7) * 4;          // k offset within tile for A loads
    const int bkrow = tid >> 5;               // 0..7
    const int bn    = (tid & 31) * 4;         // n offset within tile for B loads
    const float* bptr = Bw + blockIdx.x*BN + bn;

    float acc[4][4][4];
    #pragma unroll
    for (int i=0;i<4;i++)
      #pragma unroll
      for (int j=0;j<4;j++)
        #pragma unroll
        for (int q=0;q<4;q++) acc[i][j][q]=0.f;

    const int ntiles = K / BK;
    float4 ar[4], br[4];

    // Prologue: tile 0 -> smem
    #pragma unroll
    for (int r=0;r<4;r++) ar[r] = *reinterpret_cast<const float4*>(aptr[r] + ak);
    #pragma unroll
    for (int r=0;r<4;r++) br[r] = *reinterpret_cast<const float4*>(bptr + (size_t)(bkrow + r*8) * NH);
    #pragma unroll
    for (int r=0;r<4;r++){
        int row = (tid>>3) + r*32;
        uint4 u = make_uint4(f2t(ar[r].x), f2t(ar[r].y), f2t(ar[r].z), f2t(ar[r].w));
        *reinterpret_cast<uint4*>(&As[row*ASTR + ak]) = u;
    }
    #pragma unroll
    for (int r=0;r<4;r++){
        int kr = bkrow + r*8;
        uint4 u = make_uint4(f2t(br[r].x), f2t(br[r].y), f2t(br[r].z), f2t(br[r].w));
        *reinterpret_cast<uint4*>(&Bs[kr*BSTR + bn]) = u;
    }
    __syncthreads();

    const int wmb = (warp>>2)*64;   // warp M base (2 warps in M)
    const int wnb = (warp&3)*32;    // warp N base (4 warps in N)

    for (int kt = 0; kt < ntiles; kt++){
        if (kt+1 < ntiles){
            int ko = (kt+1)*BK;
            #pragma unroll
            for (int r=0;r<4;r++) ar[r] = *reinterpret_cast<const float4*>(aptr[r] + ko + ak);
            #pragma unroll
            for (int r=0;r<4;r++) br[r] = *reinterpret_cast<const float4*>(bptr + (size_t)(ko + bkrow + r*8) * NH);
        }
        #pragma unroll
        for (int kk = 0; kk < BK; kk += 8){
            uint32_t af[4][4], bf[4][2];
            #pragma unroll
            for (int mi=0; mi<4; mi++){
                int mr = wmb + mi*16 + group;
                af[mi][0] = As[mr*ASTR     + kk + tid4];
                af[mi][1] = As[(mr+8)*ASTR + kk + tid4];
                af[mi][2] = As[mr*ASTR     + kk + tid4 + 4];
                af[mi][3] = As[(mr+8)*ASTR + kk + tid4 + 4];
            }
            #pragma unroll
            for (int ni=0; ni<4; ni++){
                int nc = wnb + ni*8 + group;
                bf[ni][0] = Bs[(kk + tid4)*BSTR     + nc];
                bf[ni][1] = Bs[(kk + tid4 + 4)*BSTR + nc];
            }
            #pragma unroll
            for (int mi=0; mi<4; mi++)
                #pragma unroll
                for (int ni=0; ni<4; ni++){
                    asm volatile(
                        "mma.sync.aligned.m16n8k8.row.col.f32.tf32.tf32.f32 "
                        "{%0,%1,%2,%3}, {%4,%5,%6,%7}, {%8,%9}, {%0,%1,%2,%3};"
                        : "+f"(acc[mi][ni][0]), "+f"(acc[mi][ni][1]),
                          "+f"(acc[mi][ni][2]), "+f"(acc[mi][ni][3])
                        : "r"(af[mi][0]), "r"(af[mi][1]), "r"(af[mi][2]), "r"(af[mi][3]),
                          "r"(bf[ni][0]), "r"(bf[ni][1]));
                }
        }
        __syncthreads();
        if (kt+1 < ntiles){
            #pragma unroll
            for (int r=0;r<4;r++){
                int row = (tid>>3) + r*32;
                uint4 u = make_uint4(f2t(ar[r].x), f2t(ar[r].y), f2t(ar[r].z), f2t(ar[r].w));
                *reinterpret_cast<uint4*>(&As[row*ASTR + ak]) = u;
            }
            #pragma unroll
            for (int r=0;r<4;r++){
                int kr = bkrow + r*8;
                uint4 u = make_uint4(f2t(br[r].x), f2t(br[r].y), f2t(br[r].z), f2t(br[r].w));
                *reinterpret_cast<uint4*>(&Bs[kr*BSTR + bn]) = u;
            }
            __syncthreads();
        }
    }

    // Epilogue
    const int m0 = blockIdx.y*BM + wmb;
    const int n0 = blockIdx.x*BN + wnb;
    #pragma unroll
    for (int mi=0; mi<4; mi++){
        #pragma unroll
        for (int ni=0; ni<4; ni++){
            int rr = m0 + mi*16 + group;
            int cc = n0 + ni*8 + tid4*2;
            #pragma unroll
            for (int q=0;q<4;q++){
                int m = rr + ((q>=2) ? 8 : 0);
                int c = cc + (q&1);
                float v = acc[mi][ni][q] + bias[c];
                size_t ci = (size_t)m*NH + c;
                if (mode == 0){
                    C[ci] = fmaxf(v, 0.f);
                } else {
                    float res = resid[ci] + v;
                    C[ci] = res;
                    int b = m >> 11, s = m & 2047;
                    out_all[(((size_t)layer*NS + s)*NB + b)*(2*NH) + colOff + c] = res;
                    if (out_last) out_last[((size_t)m)*(2*NH) + colOff + c] = res;
                }
            }
        }
    }
}

// LayerNorm: one warp per 512-float row.
__global__ void ln_kernel(const float* __restrict__ x, const float* __restrict__ g,
                          const float* __restrict__ beta, float* __restrict__ y){
    int row  = blockIdx.x*8 + (threadIdx.x >> 5);
    int lane = threadIdx.x & 31;
    const float4* xr = reinterpret_cast<const float4*>(x + (size_t)row*NH);
    float4 v[4];
    float s = 0.f, ss = 0.f;
    #pragma unroll
    for (int i=0;i<4;i++){
        v[i] = xr[lane + i*32];
        s  += v[i].x + v[i].y + v[i].z + v[i].w;
        ss += v[i].x*v[i].x + v[i].y*v[i].y + v[i].z*v[i].z + v[i].w*v[i].w;
    }
    #pragma unroll
    for (int o=16;o>0;o>>=1){
        s  += __shfl_xor_sync(0xffffffff, s,  o);
        ss += __shfl_xor_sync(0xffffffff, ss, o);
    }
    float mean = s  * (1.f/NH);
    float var  = ss * (1.f/NH) - mean*mean;
    float rstd = rsqrtf(var + LN_EPS);
    float4* yr = reinterpret_cast<float4*>(y + (size_t)row*NH);
    #pragma unroll
    for (int i=0;i<4;i++){
        int c = (lane + i*32)*4;
        float4 o;
        o.x = g[c+0]*((v[i].x-mean)*rstd) + beta[c+0];
        o.y = g[c+1]*((v[i].y-mean)*rstd) + beta[c+1];
        o.z = g[c+2]*((v[i].z-mean)*rstd) + beta[c+2];
        o.w = g[c+3]*((v[i].w-mean)*rstd) + beta[c+3];
        yr[lane + i*32] = o;
    }
}

extern "C" void kernel_launch(void* const* d_in, const int* in_sizes, int n_in,
                              void* d_out, int out_size){
    const float* inputs = (const float*)d_in[0];
    const float* lp  = (const float*)d_in[1];
    const float* rp  = (const float*)d_in[2];
    const float* Wl  = (const float*)d_in[3];
    const float* bl  = (const float*)d_in[4];
    const float* Wr  = (const float*)d_in[5];
    const float* br_ = (const float*)d_in[6];
    const float* lw1 = (const float*)d_in[7];
    const float* lb1 = (const float*)d_in[8];
    const float* lw2 = (const float*)d_in[9];
    const float* lb2 = (const float*)d_in[10];
    const float* lg  = (const float*)d_in[11];
    const float* lbe = (const float*)d_in[12];
    const float* rw1 = (const float*)d_in[13];
    const float* rb1 = (const float*)d_in[14];
    const float* rw2 = (const float*)d_in[15];
    const float* rb2 = (const float*)d_in[16];
    const float* rg  = (const float*)d_in[17];
    const float* rbe = (const float*)d_in[18];

    float* out_all  = (float*)d_out;
    float* out_last = out_all + (size_t)NL*NS*NB*2*NH;

    float *p_pad, *p_lo, *p_ro, *p_tmp, *p_hid;
    cudaGetSymbolAddress((void**)&p_pad, g_padded);
    cudaGetSymbolAddress((void**)&p_lo,  g_lo);
    cudaGetSymbolAddress((void**)&p_ro,  g_ro);
    cudaGetSymbolAddress((void**)&p_tmp, g_tmp);
    cudaGetSymbolAddress((void**)&p_hid, g_hid);

    int padN = NB*NSP*(NH/4);
    build_padded_kernel<<<(padN+255)/256, 256>>>(inputs, lp, rp);

    dim3 gg(NH/BN, (NB*NS)/BM);   // (4, 256)

    // Projections: lo = relu(left @ Wl + bl), ro = relu(right @ Wr + br)
    gemm_tf32_kernel<<<gg, NTHREADS>>>(p_pad, Wl,  bl,  p_lo, nullptr, nullptr, nullptr, NW*NH, 1, 0, 0, 0);
    gemm_tf32_kernel<<<gg, NTHREADS>>>(p_pad, Wr,  br_, p_ro, nullptr, nullptr, nullptr, NW*NH, 2, 0, 0, 0);

    for (int i = 0; i < NL; i++){
        float* lastp = (i == NL-1) ? out_last : nullptr;
        // left
        ln_kernel<<<(NB*NS)/8, 256>>>(p_lo, lg + i*NH, lbe + i*NH, p_tmp);
        gemm_tf32_kernel<<<gg, NTHREADS>>>(p_tmp, lw1 + (size_t)i*NH*NH, lb1 + i*NH, p_hid,
                                           nullptr, nullptr, nullptr, NH, 0, 0, 0, 0);
        gemm_tf32_kernel<<<gg, NTHREADS>>>(p_hid, lw2 + (size_t)i*NH*NH, lb2 + i*NH, p_lo,
                                           p_lo, out_all, lastp, NH, 0, 1, 0, i);
        // right
        ln_kernel<<<(NB*NS)/8, 256>>>(p_ro, rg + i*NH, rbe + i*NH, p_tmp);
        gemm_tf32_kernel<<<gg, NTHREADS>>>(p_tmp, rw1 + (size_t)i*NH*NH, rb1 + i*NH, p_hid,
                                           nullptr, nullptr, nullptr, NH, 0, 0, 0, 0);
        gemm_tf32_kernel<<<gg, NTHREADS>>>(p_hid, rw2 + (size_t)i*NH*NH, rb2 + i*NH, p_ro,
                                           p_ro, out_all, lastp, NH, 0, 1, NH, i);
    }
}